// round 5
// baseline (speedup 1.0000x reference)
#include <cuda_runtime.h>
#include <cstdint>
#include <math.h>

#define S_TOT 3328
#define S_TXT 256
#define S_IMG 3072
#define DM    1920
#define NH    30
#define HD    64

// Scratch (device globals: allocation-free per harness rules)
__device__ float g_Q[(size_t)S_TOT * DM];
__device__ float g_K[(size_t)S_TOT * DM];
__device__ float g_V[(size_t)S_TOT * DM];
__device__ float g_O[(size_t)S_TOT * DM];
__device__ float g_A[(size_t)S_TOT * DM];          // tf32-rounded concat(enc,hid)
__device__ float g_W[4][(size_t)DM * DM];          // tf32-rounded Wq,Wk,Wv,Wo

__device__ __forceinline__ float to_tf32(float x) {
    uint32_t b;
    asm("cvt.rna.tf32.f32 %0, %1;" : "=r"(b) : "f"(x));
    return __uint_as_float(b);
}

// m16n8k8 tf32 HMMA (sm_80+; valid on sm_103 base target)
__device__ __forceinline__ void mma_tf32(float* d,
    float a0, float a1, float a2, float a3, float b0, float b1)
{
    asm volatile(
        "mma.sync.aligned.m16n8k8.row.col.f32.tf32.tf32.f32 "
        "{%0,%1,%2,%3}, {%4,%5,%6,%7}, {%8,%9}, {%0,%1,%2,%3};"
        : "+f"(d[0]), "+f"(d[1]), "+f"(d[2]), "+f"(d[3])
        : "r"(__float_as_uint(a0)), "r"(__float_as_uint(a1)),
          "r"(__float_as_uint(a2)), "r"(__float_as_uint(a3)),
          "r"(__float_as_uint(b0)), "r"(__float_as_uint(b1)));
}

// ===========================================================================
// tf32 round-to-nearest copy (float4 granular)
// ===========================================================================
__global__ __launch_bounds__(256) void tf32_round(
    const float* __restrict__ src, float* __restrict__ dst, int n4)
{
    int i = blockIdx.x * blockDim.x + threadIdx.x;
    if (i < n4) {
        float4 v = ((const float4*)src)[i];
        v.x = to_tf32(v.x); v.y = to_tf32(v.y);
        v.z = to_tf32(v.z); v.w = to_tf32(v.w);
        ((float4*)dst)[i] = v;
    }
}

// ===========================================================================
// HMMA tf32 GEMM: C[m,n] = sum_k A[m,k]*W[n,k] + bias[n]
// CTA 128x128, BK=16, double-buffered cp.async. 8 warps (4x2), warp tile
// 32x64. SMEM stride 20 floats -> conflict-free fragment LDS.
// swap_mode: remap output rows (txt <-> img blocks) for the final projection.
// ===========================================================================
#define SSTRIDE 20

__global__ __launch_bounds__(256) void gemm_mma(
    const float* __restrict__ A, const float* __restrict__ W,
    const float* __restrict__ bias, float* __restrict__ C, int swap_mode)
{
    __shared__ float As[2][128][SSTRIDE];
    __shared__ float Bs[2][128][SSTRIDE];

    const int tid  = threadIdx.x;
    const int lane = tid & 31;
    const int warp = tid >> 5;
    const int wm   = (warp >> 1) * 32;   // warp row offset in tile
    const int wn   = (warp & 1) * 64;    // warp col offset in tile
    const int m0   = blockIdx.y * 128;
    const int n0   = blockIdx.x * 128;

    const int lrow = tid >> 2;           // 0..63: row pair loader
    const int lchk = tid & 3;            // 16B chunk within 64B row segment

    float acc[2][8][4];
    #pragma unroll
    for (int i = 0; i < 2; i++)
        #pragma unroll
        for (int j = 0; j < 8; j++)
            #pragma unroll
            for (int c = 0; c < 4; c++) acc[i][j][c] = 0.f;

    // ---- async tile loader: 128 rows x 16 floats (64B = 4 chunks) each ----
    auto load_stage = [&](int s, int kt) {
        int kg = kt * 16 + lchk * 4;
        #pragma unroll
        for (int h = 0; h < 2; h++) {
            int row = lrow + h * 64;
            const float* ga = A + (size_t)(m0 + row) * DM + kg;
            const float* gb = W + (size_t)(n0 + row) * DM + kg;
            uint32_t sa, sb_;
            asm("{ .reg .u64 t; cvta.to.shared.u64 t, %1; cvt.u32.u64 %0, t; }"
                : "=r"(sa) : "l"(&As[s][row][lchk * 4]));
            asm("{ .reg .u64 t; cvta.to.shared.u64 t, %1; cvt.u32.u64 %0, t; }"
                : "=r"(sb_) : "l"(&Bs[s][row][lchk * 4]));
            asm volatile("cp.async.cg.shared.global [%0], [%1], 16;" :: "r"(sa), "l"(ga) : "memory");
            asm volatile("cp.async.cg.shared.global [%0], [%1], 16;" :: "r"(sb_), "l"(gb) : "memory");
        }
    };

    load_stage(0, 0);
    asm volatile("cp.async.commit_group;" ::: "memory");

    const int NKT = DM / 16;   // 120
    for (int kt = 0; kt < NKT; kt++) {
        int s = kt & 1;
        if (kt + 1 < NKT) {
            load_stage(s ^ 1, kt + 1);
            asm volatile("cp.async.commit_group;" ::: "memory");
            asm volatile("cp.async.wait_group 1;" ::: "memory");
        } else {
            asm volatile("cp.async.wait_group 0;" ::: "memory");
        }
        __syncthreads();

        #pragma unroll
        for (int ks = 0; ks < 16; ks += 8) {
            int cA = ks + (lane & 3);
            float a[2][4];
            #pragma unroll
            for (int i = 0; i < 2; i++) {
                int r = wm + i * 16 + (lane >> 2);
                a[i][0] = As[s][r][cA];
                a[i][1] = As[s][r + 8][cA];
                a[i][2] = As[s][r][cA + 4];
                a[i][3] = As[s][r + 8][cA + 4];
            }
            #pragma unroll
            for (int j = 0; j < 8; j++) {
                int r = wn + j * 8 + (lane >> 2);
                float b0 = Bs[s][r][cA];
                float b1 = Bs[s][r][cA + 4];
                mma_tf32(acc[0][j], a[0][0], a[0][1], a[0][2], a[0][3], b0, b1);
                mma_tf32(acc[1][j], a[1][0], a[1][1], a[1][2], a[1][3], b0, b1);
            }
        }
        __syncthreads();
    }

    // ---- epilogue ----
    #pragma unroll
    for (int i = 0; i < 2; i++) {
        int row_lo = m0 + wm + i * 16 + (lane >> 2);
        #pragma unroll
        for (int half = 0; half < 2; half++) {
            int row = row_lo + half * 8;
            size_t orow = (size_t)row;
            if (swap_mode)
                orow = (row < S_TXT) ? (size_t)(S_IMG + row) : (size_t)(row - S_TXT);
            float* dst = C + orow * DM + n0 + wn;
            #pragma unroll
            for (int j = 0; j < 8; j++) {
                int col = j * 8 + (lane & 3) * 2;
                float2 o;
                o.x = acc[i][j][half * 2 + 0] + __ldg(bias + n0 + wn + col);
                o.y = acc[i][j][half * 2 + 1] + __ldg(bias + n0 + wn + col + 1);
                *(float2*)(dst + col) = o;
            }
        }
    }
}

// ---------------------------------------------------------------------------
// LayerNorm (fp32, per (s,h) over hd=64) + RoPE on image tokens. In place.
// ---------------------------------------------------------------------------
__global__ __launch_bounds__(256) void ln_rope(
    const float* __restrict__ cosb, const float* __restrict__ sinb, int which)
{
    float* __restrict__ X = which ? g_K : g_Q;
    int w = blockIdx.x * 8 + (threadIdx.x >> 5);
    int lane = threadIdx.x & 31;
    int s = w / NH;
    int h = w - s * NH;
    if (s >= S_TOT) return;

    float* p = X + (size_t)s * DM + h * HD;
    float x0 = p[lane], x1 = p[lane + 32];

    float sum = x0 + x1;
    #pragma unroll
    for (int o = 16; o; o >>= 1) sum += __shfl_xor_sync(0xffffffffu, sum, o);
    float mu = sum * (1.0f / 64.0f);

    float d0 = x0 - mu, d1 = x1 - mu;
    float vs = fmaf(d0, d0, d1 * d1);
    #pragma unroll
    for (int o = 16; o; o >>= 1) vs += __shfl_xor_sync(0xffffffffu, vs, o);
    float inv = rsqrtf(fmaf(vs, 1.0f / 64.0f, 1e-5f));

    float y0 = d0 * inv, y1 = d1 * inv;

    if (s >= S_TXT) {
        int sp = s - S_TXT;
        const float* cr = cosb + (size_t)sp * HD;
        const float* sr = sinb + (size_t)sp * HD;
        float c0 = cr[lane], c1 = cr[lane + 32];
        float s0 = sr[lane], s1 = sr[lane + 32];
        float o0 = fmaf(y0, c0, -y1 * s0);
        float o1 = fmaf(y1, c1,  y0 * s1);
        y0 = o0; y1 = o1;
    }
    p[lane] = y0;
    p[lane + 32] = y1;
}

// ---------------------------------------------------------------------------
// Flash attention (fp32 FFMA): CTA = (64-query block, head). Online softmax.
// ---------------------------------------------------------------------------
__global__ __launch_bounds__(256) void attn_kernel()
{
    __shared__ float Qs[64][64];  // [d][qrow]
    __shared__ float KP[64][64];  // K as [d][key], then P as [key][qrow]
    __shared__ float Vs[64][64];  // [key][d]

    const int h  = blockIdx.y;
    const int m0 = blockIdx.x * 64;
    const int tid = threadIdx.x;
    const int ty = tid >> 4, tx = tid & 15;

    #pragma unroll
    for (int it = 0; it < 4; it++) {
        int f = tid + it * 256;
        int row = f >> 4;
        int d4  = (f & 15) * 4;
        float4 v = *(const float4*)(g_Q + (size_t)(m0 + row) * DM + h * HD + d4);
        Qs[d4+0][row] = v.x; Qs[d4+1][row] = v.y; Qs[d4+2][row] = v.z; Qs[d4+3][row] = v.w;
    }

    float m[4], l[4], acc[4][4];
    #pragma unroll
    for (int i = 0; i < 4; i++) {
        m[i] = -3.4e38f; l[i] = 0.f;
        #pragma unroll
        for (int j = 0; j < 4; j++) acc[i][j] = 0.f;
    }

    for (int n0 = 0; n0 < S_TOT; n0 += 64) {
        __syncthreads();
        #pragma unroll
        for (int it = 0; it < 4; it++) {
            int f = tid + it * 256;
            int row = f >> 4;
            int d4  = (f & 15) * 4;
            size_t gidx = (size_t)(n0 + row) * DM + h * HD + d4;
            float4 kv = *(const float4*)(g_K + gidx);
            KP[d4+0][row] = kv.x; KP[d4+1][row] = kv.y; KP[d4+2][row] = kv.z; KP[d4+3][row] = kv.w;
            float4 vv = *(const float4*)(g_V + gidx);
            *(float4*)&Vs[row][d4] = vv;
        }
        __syncthreads();

        float s_[4][4];
        #pragma unroll
        for (int i = 0; i < 4; i++)
            #pragma unroll
            for (int j = 0; j < 4; j++) s_[i][j] = 0.f;

        #pragma unroll 16
        for (int d = 0; d < 64; d++) {
            float4 q  = *(const float4*)&Qs[d][ty*4];
            float4 kk = *(const float4*)&KP[d][tx*4];
            float qa[4] = {q.x, q.y, q.z, q.w};
            float ka[4] = {kk.x, kk.y, kk.z, kk.w};
            #pragma unroll
            for (int i = 0; i < 4; i++)
                #pragma unroll
                for (int j = 0; j < 4; j++)
                    s_[i][j] = fmaf(qa[i], ka[j], s_[i][j]);
        }

        const float sc = 0.125f;
        #pragma unroll
        for (int i = 0; i < 4; i++) {
            #pragma unroll
            for (int j = 0; j < 4; j++) s_[i][j] *= sc;

            float rmax = fmaxf(fmaxf(s_[i][0], s_[i][1]), fmaxf(s_[i][2], s_[i][3]));
            #pragma unroll
            for (int o = 1; o < 16; o <<= 1)
                rmax = fmaxf(rmax, __shfl_xor_sync(0xffffffffu, rmax, o));

            float mn = fmaxf(m[i], rmax);
            float corr = __expf(m[i] - mn);
            float rsum = 0.f;
            #pragma unroll
            for (int j = 0; j < 4; j++) {
                s_[i][j] = __expf(s_[i][j] - mn);
                rsum += s_[i][j];
            }
            #pragma unroll
            for (int o = 1; o < 16; o <<= 1)
                rsum += __shfl_xor_sync(0xffffffffu, rsum, o);

            l[i] = l[i] * corr + rsum;
            m[i] = mn;
            #pragma unroll
            for (int j = 0; j < 4; j++) acc[i][j] *= corr;
        }

        __syncthreads();
        #pragma unroll
        for (int i = 0; i < 4; i++)
            #pragma unroll
            for (int j = 0; j < 4; j++)
                KP[tx*4 + j][ty*4 + i] = s_[i][j];
        __syncthreads();

        #pragma unroll 16
        for (int kk2 = 0; kk2 < 64; kk2++) {
            float4 p4 = *(const float4*)&KP[kk2][ty*4];
            float4 v4 = *(const float4*)&Vs[kk2][tx*4];
            float pa[4] = {p4.x, p4.y, p4.z, p4.w};
            float va[4] = {v4.x, v4.y, v4.z, v4.w};
            #pragma unroll
            for (int i = 0; i < 4; i++)
                #pragma unroll
                for (int j = 0; j < 4; j++)
                    acc[i][j] = fmaf(pa[i], va[j], acc[i][j]);
        }
    }

    #pragma unroll
    for (int i = 0; i < 4; i++) {
        int gm = m0 + ty*4 + i;
        float inv = 1.0f / l[i];
        float4 o;
        o.x = acc[i][0] * inv; o.y = acc[i][1] * inv;
        o.z = acc[i][2] * inv; o.w = acc[i][3] * inv;
        *(float4*)(g_O + (size_t)gm * DM + h * HD + tx*4) = o;
    }
}

// ---------------------------------------------------------------------------
extern "C" void kernel_launch(void* const* d_in, const int* in_sizes, int n_in,
                              void* d_out, int out_size)
{
    const float* hid = (const float*)d_in[0];
    const float* enc = (const float*)d_in[1];
    const float* rc  = (const float*)d_in[2];
    const float* rs  = (const float*)d_in[3];
    const float* Wq  = (const float*)d_in[4];
    const float* bq  = (const float*)d_in[5];
    const float* Wk  = (const float*)d_in[6];
    const float* bk  = (const float*)d_in[7];
    const float* Wv  = (const float*)d_in[8];
    const float* bv  = (const float*)d_in[9];
    const float* Wo  = (const float*)d_in[10];
    const float* bo  = (const float*)d_in[11];
    float* out = (float*)d_out;

    float* pA; cudaGetSymbolAddress((void**)&pA, g_A);
    float* pW; cudaGetSymbolAddress((void**)&pW, g_W);
    float* pQ; cudaGetSymbolAddress((void**)&pQ, g_Q);
    float* pK; cudaGetSymbolAddress((void**)&pK, g_K);
    float* pV; cudaGetSymbolAddress((void**)&pV, g_V);
    float* pO; cudaGetSymbolAddress((void**)&pO, g_O);

    // tf32 round-to-nearest prep (so HMMA truncation is exact / unbiased)
    tf32_round<<<(S_TXT*DM/4 + 255)/256, 256>>>(enc, pA, S_TXT*DM/4);
    tf32_round<<<(S_IMG*DM/4 + 255)/256, 256>>>(hid, pA + (size_t)S_TXT*DM, S_IMG*DM/4);
    tf32_round<<<(DM*DM/4 + 255)/256, 256>>>(Wq, pW + 0*(size_t)DM*DM, DM*DM/4);
    tf32_round<<<(DM*DM/4 + 255)/256, 256>>>(Wk, pW + 1*(size_t)DM*DM, DM*DM/4);
    tf32_round<<<(DM*DM/4 + 255)/256, 256>>>(Wv, pW + 2*(size_t)DM*DM, DM*DM/4);
    tf32_round<<<(DM*DM/4 + 255)/256, 256>>>(Wo, pW + 3*(size_t)DM*DM, DM*DM/4);

    dim3 gGemm(DM / 128, S_TOT / 128);          // (15, 26)
    gemm_mma<<<gGemm, 256>>>(pA, pW + 0*(size_t)DM*DM, bq, pQ, 0);
    gemm_mma<<<gGemm, 256>>>(pA, pW + 1*(size_t)DM*DM, bk, pK, 0);
    gemm_mma<<<gGemm, 256>>>(pA, pW + 2*(size_t)DM*DM, bv, pV, 0);

    int nblk = (S_TOT * NH) / 8;
    ln_rope<<<nblk, 256>>>(rc, rs, 0);
    ln_rope<<<nblk, 256>>>(rc, rs, 1);

    attn_kernel<<<dim3(S_TOT / 64, NH), 256>>>();

    tf32_round<<<(S_TOT*DM/4 + 255)/256, 256>>>(pO, pO, S_TOT*DM/4);
    gemm_mma<<<gGemm, 256>>>(pO, pW + 3*(size_t)DM*DM, bo, out, 1);
}

// round 7
// speedup vs baseline: 1.3333x; 1.3333x over previous
#include <cuda_runtime.h>
#include <cstdint>
#include <math.h>

#define S_TOT 3328
#define S_TXT 256
#define S_IMG 3072
#define DM    1920
#define NH    30
#define HD    64
#define QSCALE 0.18033688011112043f  // 0.125*log2(e)

__device__ float g_Q[(size_t)S_TOT * DM];
__device__ float g_K[(size_t)S_TOT * DM];   // Khi after ln_rope
__device__ float g_Kl[(size_t)S_TOT * DM];  // Klo after ln_rope
__device__ float g_V[(size_t)S_TOT * DM];
__device__ float g_O[(size_t)S_TOT * DM];

__device__ __forceinline__ float to_tf32(float x) {
    uint32_t b; asm("cvt.rna.tf32.f32 %0, %1;" : "=r"(b) : "f"(x));
    return __uint_as_float(b);
}
__device__ __forceinline__ float ex2(float x) {
    float r; asm("ex2.approx.f32 %0, %1;" : "=f"(r) : "f"(x)); return r;
}
__device__ __forceinline__ uint32_t smem_u32(const void* p) {
    uint32_t a;
    asm("{ .reg .u64 t; cvta.to.shared.u64 t, %1; cvt.u32.u64 %0, t; }" : "=r"(a) : "l"(p));
    return a;
}
__device__ __forceinline__ void mma_tf32(float* d,
    float a0, float a1, float a2, float a3, float b0, float b1)
{
    asm volatile(
        "mma.sync.aligned.m16n8k8.row.col.f32.tf32.tf32.f32 "
        "{%0,%1,%2,%3}, {%4,%5,%6,%7}, {%8,%9}, {%0,%1,%2,%3};"
        : "+f"(d[0]), "+f"(d[1]), "+f"(d[2]), "+f"(d[3])
        : "r"(__float_as_uint(a0)), "r"(__float_as_uint(a1)),
          "r"(__float_as_uint(a2)), "r"(__float_as_uint(a3)),
          "r"(__float_as_uint(b0)), "r"(__float_as_uint(b1)));
}
#define CPASYNC16(saddr, gptr) \
    asm volatile("cp.async.cg.shared.global [%0], [%1], 16;" :: "r"(saddr), "l"(gptr) : "memory")
#define CPCOMMIT() asm volatile("cp.async.commit_group;" ::: "memory")
#define CPWAIT(n)  asm volatile("cp.async.wait_group %0;" :: "n"(n) : "memory")

// ============== split-tf32 (3-term) GEMM, 4-stage cp.async pipeline ========
// C[m,n] = sum_k A[m,k]*W[n,k] + bias[n], near-fp32 accurate.
#define GSTRIDE 20
#define GSTAGE  (128 * GSTRIDE)
#define GEMM_SMEM_BYTES (8 * GSTAGE * 4)

__global__ __launch_bounds__(256, 2) void gemm_mma(
    const float* __restrict__ hid, const float* __restrict__ enc,
    const float* __restrict__ W, const float* __restrict__ bias,
    float* __restrict__ C, int concat_mode, int swap_mode, int round_out)
{
    extern __shared__ float dsm[];
    float* As = dsm;
    float* Bs = dsm + 4 * GSTAGE;
    const int tid = threadIdx.x, lane = tid & 31, warp = tid >> 5;
    const int wm = (warp >> 1) * 32, wn = (warp & 1) * 64;
    const int m0 = blockIdx.y * 128, n0 = blockIdx.x * 128;
    const int lrow = tid >> 2, lchk = tid & 3;
    const uint32_t sbA = smem_u32(As), sbB = smem_u32(Bs);

    // per-thread A row bases (handles concat of enc|hid)
    const float* abase[2];
    const float* bbase[2];
    #pragma unroll
    for (int hh = 0; hh < 2; hh++) {
        int gm = m0 + lrow + hh * 64;
        abase[hh] = concat_mode
            ? ((gm < S_TXT) ? enc + (size_t)gm * DM : hid + (size_t)(gm - S_TXT) * DM)
            : hid + (size_t)gm * DM;
        bbase[hh] = W + (size_t)(n0 + lrow + hh * 64) * DM;
    }

    float acc[2][8][4];
    #pragma unroll
    for (int i = 0; i < 2; i++)
        #pragma unroll
        for (int j = 0; j < 8; j++)
            #pragma unroll
            for (int c = 0; c < 4; c++) acc[i][j][c] = 0.f;

    auto load_stage = [&](int buf, int kt) {
        int kg = kt * 16 + lchk * 4;
        #pragma unroll
        for (int hh = 0; hh < 2; hh++) {
            uint32_t off = (buf * GSTAGE + (lrow + hh * 64) * GSTRIDE + lchk * 4) * 4;
            CPASYNC16(sbA + off, abase[hh] + kg);
            CPASYNC16(sbB + off, bbase[hh] + kg);
        }
    };

    const int NKT = DM / 16;  // 120
    #pragma unroll
    for (int p = 0; p < 3; p++) { load_stage(p, p); CPCOMMIT(); }

    for (int kt = 0; kt < NKT; kt++) {
        int s = kt & 3;
        CPWAIT(2);
        __syncthreads();
        if (kt + 3 < NKT) load_stage((kt + 3) & 3, kt + 3);
        CPCOMMIT();

        const float* Ab = As + s * GSTAGE;
        const float* Bb = Bs + s * GSTAGE;
        #pragma unroll
        for (int ks = 0; ks < 16; ks += 8) {
            int cA = ks + (lane & 3);
            float ahi[2][4], alo[2][4];
            #pragma unroll
            for (int i = 0; i < 2; i++) {
                int r = wm + i * 16 + (lane >> 2);
                float a0 = Ab[r * GSTRIDE + cA];
                float a1 = Ab[(r + 8) * GSTRIDE + cA];
                float a2 = Ab[r * GSTRIDE + cA + 4];
                float a3 = Ab[(r + 8) * GSTRIDE + cA + 4];
                ahi[i][0] = to_tf32(a0); alo[i][0] = to_tf32(a0 - ahi[i][0]);
                ahi[i][1] = to_tf32(a1); alo[i][1] = to_tf32(a1 - ahi[i][1]);
                ahi[i][2] = to_tf32(a2); alo[i][2] = to_tf32(a2 - ahi[i][2]);
                ahi[i][3] = to_tf32(a3); alo[i][3] = to_tf32(a3 - ahi[i][3]);
            }
            #pragma unroll
            for (int j = 0; j < 8; j++) {
                int r = wn + j * 8 + (lane >> 2);
                float b0 = Bb[r * GSTRIDE + cA];
                float b1 = Bb[r * GSTRIDE + cA + 4];
                float bh0 = to_tf32(b0), bl0 = to_tf32(b0 - bh0);
                float bh1 = to_tf32(b1), bl1 = to_tf32(b1 - bh1);
                #pragma unroll
                for (int i = 0; i < 2; i++) {
                    mma_tf32(acc[i][j], ahi[i][0], ahi[i][1], ahi[i][2], ahi[i][3], bh0, bh1);
                    mma_tf32(acc[i][j], alo[i][0], alo[i][1], alo[i][2], alo[i][3], bh0, bh1);
                    mma_tf32(acc[i][j], ahi[i][0], ahi[i][1], ahi[i][2], ahi[i][3], bl0, bl1);
                }
            }
        }
    }

    #pragma unroll
    for (int i = 0; i < 2; i++) {
        int row_lo = m0 + wm + i * 16 + (lane >> 2);
        #pragma unroll
        for (int half = 0; half < 2; half++) {
            int row = row_lo + half * 8;
            size_t orow = (size_t)row;
            if (swap_mode)
                orow = (row < S_TXT) ? (size_t)(S_IMG + row) : (size_t)(row - S_TXT);
            float* dst = C + orow * DM + n0 + wn;
            #pragma unroll
            for (int j = 0; j < 8; j++) {
                int col = j * 8 + (lane & 3) * 2;
                float2 o;
                o.x = acc[i][j][half * 2 + 0] + __ldg(bias + n0 + wn + col);
                o.y = acc[i][j][half * 2 + 1] + __ldg(bias + n0 + wn + col + 1);
                if (round_out) { o.x = to_tf32(o.x); o.y = to_tf32(o.y); }
                *(float2*)(dst + col) = o;
            }
        }
    }
}

// ======= LayerNorm + RoPE; K is split into (Khi -> g_K, Klo -> g_Kl) =======
__global__ __launch_bounds__(256) void ln_rope(
    const float* __restrict__ cosb, const float* __restrict__ sinb, int which)
{
    float* __restrict__ X = which ? g_K : g_Q;
    int w = blockIdx.x * 8 + (threadIdx.x >> 5);
    int lane = threadIdx.x & 31;
    int s = w / NH, h = w - s * NH;
    if (s >= S_TOT) return;

    size_t off = (size_t)s * DM + h * HD;
    float* p = X + off;
    float x0 = p[lane], x1 = p[lane + 32];
    float sum = x0 + x1;
    #pragma unroll
    for (int o = 16; o; o >>= 1) sum += __shfl_xor_sync(0xffffffffu, sum, o);
    float mu = sum * (1.0f / 64.0f);
    float d0 = x0 - mu, d1 = x1 - mu;
    float vs = fmaf(d0, d0, d1 * d1);
    #pragma unroll
    for (int o = 16; o; o >>= 1) vs += __shfl_xor_sync(0xffffffffu, vs, o);
    float inv = rsqrtf(fmaf(vs, 1.0f / 64.0f, 1e-5f));
    float y0 = d0 * inv, y1 = d1 * inv;

    if (s >= S_TXT) {
        int sp = s - S_TXT;
        const float* cr = cosb + (size_t)sp * HD;
        const float* sr = sinb + (size_t)sp * HD;
        float c0 = cr[lane], c1 = cr[lane + 32];
        float s0 = sr[lane], s1 = sr[lane + 32];
        float o0 = fmaf(y0, c0, -y1 * s0);
        float o1 = fmaf(y1, c1,  y0 * s1);
        y0 = o0; y1 = o1;
    }
    if (which) {
        float h0 = to_tf32(y0), h1 = to_tf32(y1);
        p[lane] = h0;       p[lane + 32] = h1;
        g_Kl[off + lane]      = to_tf32(y0 - h0);
        g_Kl[off + lane + 32] = to_tf32(y1 - h1);
    } else {
        p[lane] = y0;
        p[lane + 32] = y1;
    }
}

// =================== split-tf32 HMMA flash attention ========================
// smem floats: Ps[128][68] | Khi[2][64][68] | Klo[2][64][68] | V[2][64][72]
#define AT_KH 8704
#define AT_KL (8704 + 8704)
#define AT_V  (8704 + 8704 + 8704)
#define ATT_SMEM_BYTES ((8704 + 8704 + 8704 + 9216) * 4)

__global__ __launch_bounds__(256, 1) void attn_mma()
{
    extern __shared__ float sm[];
    float* Ps = sm;
    const int h = blockIdx.y, m0 = blockIdx.x * 128;
    const int tid = threadIdx.x, lane = tid & 31, warp = tid >> 5;
    const int wm = warp * 16, r0 = lane >> 2, c0 = lane & 3;
    const uint32_t sKH = smem_u32(sm + AT_KH), sKL = smem_u32(sm + AT_KL),
                   sV  = smem_u32(sm + AT_V);
    const float* KH = sm + AT_KH;
    const float* KL = sm + AT_KL;
    const float* Vs = sm + AT_V;

    // Q fragments: scaled, split hi/lo
    float qh[8][4], ql[8][4];
    const float* qb = g_Q + (size_t)(m0 + wm) * DM + h * HD;
    #pragma unroll
    for (int ks = 0; ks < 8; ks++) {
        int col = ks * 8 + c0;
        float v0 = QSCALE * qb[(size_t)r0 * DM + col];
        float v1 = QSCALE * qb[(size_t)(r0 + 8) * DM + col];
        float v2 = QSCALE * qb[(size_t)r0 * DM + col + 4];
        float v3 = QSCALE * qb[(size_t)(r0 + 8) * DM + col + 4];
        qh[ks][0] = to_tf32(v0); ql[ks][0] = to_tf32(v0 - qh[ks][0]);
        qh[ks][1] = to_tf32(v1); ql[ks][1] = to_tf32(v1 - qh[ks][1]);
        qh[ks][2] = to_tf32(v2); ql[ks][2] = to_tf32(v2 - qh[ks][2]);
        qh[ks][3] = to_tf32(v3); ql[ks][3] = to_tf32(v3 - qh[ks][3]);
    }

    float out[8][4];
    #pragma unroll
    for (int j = 0; j < 8; j++)
        #pragma unroll
        for (int c = 0; c < 4; c++) out[j][c] = 0.f;
    float mx0 = -1e30f, mx1 = -1e30f, l0 = 0.f, l1 = 0.f;

    auto load_kv = [&](int buf, int t) {
        int n0 = t * 64;
        #pragma unroll
        for (int i = 0; i < 4; i++) {
            int f = tid + 256 * i, row = f >> 4, ch = f & 15;
            size_t g = (size_t)(n0 + row) * DM + h * HD + ch * 4;
            CPASYNC16(sKH + (buf * 4352 + row * 68 + ch * 4) * 4, g_K + g);
            CPASYNC16(sKL + (buf * 4352 + row * 68 + ch * 4) * 4, g_Kl + g);
            CPASYNC16(sV  + (buf * 4608 + row * 72 + ch * 4) * 4, g_V + g);
        }
        CPCOMMIT();
    };
    load_kv(0, 0);

    const int NT = S_TOT / 64;  // 52
    for (int t = 0; t < NT; t++) {
        int buf = t & 1;
        CPWAIT(0);
        __syncthreads();
        if (t + 1 < NT) load_kv(buf ^ 1, t + 1);   // buf^1 reads ended pre-barrier

        // scores = Q @ K^T (log2 domain), 3-term split
        float s_[8][4];
        #pragma unroll
        for (int j = 0; j < 8; j++)
            #pragma unroll
            for (int c = 0; c < 4; c++) s_[j][c] = 0.f;
        const float* KHb = KH + buf * 4352;
        const float* KLb = KL + buf * 4352;
        #pragma unroll
        for (int ks = 0; ks < 8; ks++) {
            int col = ks * 8 + c0;
            #pragma unroll
            for (int j = 0; j < 8; j++) {
                int rb = (j * 8 + r0) * 68;
                float bh0 = KHb[rb + col], bh1 = KHb[rb + col + 4];
                float bl0 = KLb[rb + col], bl1 = KLb[rb + col + 4];
                mma_tf32(s_[j], qh[ks][0], qh[ks][1], qh[ks][2], qh[ks][3], bh0, bh1);
                mma_tf32(s_[j], ql[ks][0], ql[ks][1], ql[ks][2], ql[ks][3], bh0, bh1);
                mma_tf32(s_[j], qh[ks][0], qh[ks][1], qh[ks][2], qh[ks][3], bl0, bl1);
            }
        }

        // online softmax: rows (wm+r0, wm+r0+8)
        float cm0 = -1e30f, cm1 = -1e30f;
        #pragma unroll
        for (int j = 0; j < 8; j++) {
            cm0 = fmaxf(cm0, fmaxf(s_[j][0], s_[j][1]));
            cm1 = fmaxf(cm1, fmaxf(s_[j][2], s_[j][3]));
        }
        cm0 = fmaxf(cm0, __shfl_xor_sync(0xffffffffu, cm0, 1));
        cm0 = fmaxf(cm0, __shfl_xor_sync(0xffffffffu, cm0, 2));
        cm1 = fmaxf(cm1, __shfl_xor_sync(0xffffffffu, cm1, 1));
        cm1 = fmaxf(cm1, __shfl_xor_sync(0xffffffffu, cm1, 2));
        float mn0 = fmaxf(mx0, cm0), mn1 = fmaxf(mx1, cm1);
        float corr0 = ex2(mx0 - mn0), corr1 = ex2(mx1 - mn1);
        mx0 = mn0; mx1 = mn1;

        float rs0 = 0.f, rs1 = 0.f;
        #pragma unroll
        for (int j = 0; j < 8; j++) {
            float p00 = to_tf32(ex2(s_[j][0] - mn0));
            float p01 = to_tf32(ex2(s_[j][1] - mn0));
            float p10 = to_tf32(ex2(s_[j][2] - mn1));
            float p11 = to_tf32(ex2(s_[j][3] - mn1));
            rs0 += p00 + p01; rs1 += p10 + p11;
            int col = j * 8 + 2 * c0;
            *(float2*)&Ps[(wm + r0) * 68 + col]     = make_float2(p00, p01);
            *(float2*)&Ps[(wm + r0 + 8) * 68 + col] = make_float2(p10, p11);
        }
        rs0 += __shfl_xor_sync(0xffffffffu, rs0, 1);
        rs0 += __shfl_xor_sync(0xffffffffu, rs0, 2);
        rs1 += __shfl_xor_sync(0xffffffffu, rs1, 1);
        rs1 += __shfl_xor_sync(0xffffffffu, rs1, 2);
        l0 = l0 * corr0 + rs0;
        l1 = l1 * corr1 + rs1;
        #pragma unroll
        for (int j = 0; j < 8; j++) {
            out[j][0] *= corr0; out[j][1] *= corr0;
            out[j][2] *= corr1; out[j][3] *= corr1;
        }
        __syncwarp();   // P rows wm..wm+15 are warp-private

        // out += P @ V  (V already rna-tf32 from V-GEMM epilogue)
        const float* Vb = Vs + buf * 4608;
        #pragma unroll
        for (int kk = 0; kk < 8; kk++) {
            int col = kk * 8 + c0;
            float a0 = Ps[(wm + r0) * 68 + col];
            float a1 = Ps[(wm + r0 + 8) * 68 + col];
            float a2 = Ps[(wm + r0) * 68 + col + 4];
            float a3 = Ps[(wm + r0 + 8) * 68 + col + 4];
            #pragma unroll
            for (int j = 0; j < 8; j++) {
                float b0 = Vb[(kk * 8 + c0) * 72 + j * 8 + r0];
                float b1 = Vb[(kk * 8 + c0 + 4) * 72 + j * 8 + r0];
                mma_tf32(out[j], a0, a1, a2, a3, b0, b1);
            }
        }
    }

    float inv0 = 1.0f / l0, inv1 = 1.0f / l1;
    int q0 = m0 + wm + r0;
    #pragma unroll
    for (int j = 0; j < 8; j++) {
        int d = j * 8 + 2 * c0;
        *(float2*)(g_O + (size_t)q0 * DM + h * HD + d) =
            make_float2(out[j][0] * inv0, out[j][1] * inv0);
        *(float2*)(g_O + (size_t)(q0 + 8) * DM + h * HD + d) =
            make_float2(out[j][2] * inv1, out[j][3] * inv1);
    }
}

// ---------------------------------------------------------------------------
extern "C" void kernel_launch(void* const* d_in, const int* in_sizes, int n_in,
                              void* d_out, int out_size)
{
    const float* hid = (const float*)d_in[0];
    const float* enc = (const float*)d_in[1];
    const float* rc  = (const float*)d_in[2];
    const float* rs  = (const float*)d_in[3];
    const float* Wq  = (const float*)d_in[4];
    const float* bq  = (const float*)d_in[5];
    const float* Wk  = (const float*)d_in[6];
    const float* bk  = (const float*)d_in[7];
    const float* Wv  = (const float*)d_in[8];
    const float* bv  = (const float*)d_in[9];
    const float* Wo  = (const float*)d_in[10];
    const float* bo  = (const float*)d_in[11];
    float* out = (float*)d_out;

    cudaFuncSetAttribute(gemm_mma, cudaFuncAttributeMaxDynamicSharedMemorySize, GEMM_SMEM_BYTES);
    cudaFuncSetAttribute(attn_mma, cudaFuncAttributeMaxDynamicSharedMemorySize, ATT_SMEM_BYTES);

    float* pQ; cudaGetSymbolAddress((void**)&pQ, g_Q);
    float* pK; cudaGetSymbolAddress((void**)&pK, g_K);
    float* pV; cudaGetSymbolAddress((void**)&pV, g_V);
    float* pO; cudaGetSymbolAddress((void**)&pO, g_O);

    dim3 gGemm(DM / 128, S_TOT / 128);   // (15, 26)
    gemm_mma<<<gGemm, 256, GEMM_SMEM_BYTES>>>(hid, enc, Wq, bq, pQ, 1, 0, 0);
    gemm_mma<<<gGemm, 256, GEMM_SMEM_BYTES>>>(hid, enc, Wk, bk, pK, 1, 0, 0);
    gemm_mma<<<gGemm, 256, GEMM_SMEM_BYTES>>>(hid, enc, Wv, bv, pV, 1, 0, 1);

    int nblk = (S_TOT * NH) / 8;
    ln_rope<<<nblk, 256>>>(rc, rs, 0);
    ln_rope<<<nblk, 256>>>(rc, rs, 1);

    // 6th launch -> profiled by ncu -s 5 -c 1
    attn_mma<<<dim3(S_TOT / 128, NH), 256, ATT_SMEM_BYTES>>>();

    gemm_mma<<<gGemm, 256, GEMM_SMEM_BYTES>>>(pO, pO, Wo, bo, out, 0, 1, 0);
}

// round 8
// speedup vs baseline: 2.0139x; 1.5104x over previous
#include <cuda_runtime.h>
#include <cuda_bf16.h>
#include <cstdint>

#define S_TOT 3328
#define S_TXT 256
#define S_IMG 3072
#define DM    1920
#define NH    30
#define HD    64
#define QSCALE 0.18033688011112043f  // 0.125*log2(e)

// fp32 scratch
__device__ float g_Q[(size_t)S_TOT * DM];
__device__ float g_K[(size_t)S_TOT * DM];
__device__ float g_V[(size_t)S_TOT * DM];
// bf16 hi/lo split operands
__device__ __nv_bfloat16 g_Ah[(size_t)S_TOT * DM];
__device__ __nv_bfloat16 g_Al[(size_t)S_TOT * DM];
__device__ __nv_bfloat16 g_Wh[4 * (size_t)DM * DM];
__device__ __nv_bfloat16 g_Wl[4 * (size_t)DM * DM];
__device__ __nv_bfloat16 g_Khb[(size_t)S_TOT * DM];
__device__ __nv_bfloat16 g_Klb[(size_t)S_TOT * DM];
__device__ __nv_bfloat16 g_Oh[(size_t)S_TOT * DM];
__device__ __nv_bfloat16 g_Ol[(size_t)S_TOT * DM];

__device__ __forceinline__ float to_tf32(float x) {
    uint32_t b; asm("cvt.rna.tf32.f32 %0, %1;" : "=r"(b) : "f"(x));
    return __uint_as_float(b);
}
__device__ __forceinline__ float ex2(float x) {
    float r; asm("ex2.approx.f32 %0, %1;" : "=f"(r) : "f"(x)); return r;
}
__device__ __forceinline__ uint32_t smem_u32(const void* p) {
    uint32_t a;
    asm("{ .reg .u64 t; cvta.to.shared.u64 t, %1; cvt.u32.u64 %0, t; }" : "=r"(a) : "l"(p));
    return a;
}
// pack two f32 -> bf16x2 reg: 'up' -> upper half, 'lo' -> lower half
__device__ __forceinline__ uint32_t pack2bf(float up, float lo) {
    uint32_t r; asm("cvt.rn.bf16x2.f32 %0, %1, %2;" : "=r"(r) : "f"(up), "f"(lo));
    return r;
}
__device__ __forceinline__ float bf_lo(uint32_t u) {
    return __bfloat162float(__ushort_as_bfloat16((unsigned short)(u & 0xFFFFu)));
}
__device__ __forceinline__ float bf_hi(uint32_t u) {
    return __bfloat162float(__ushort_as_bfloat16((unsigned short)(u >> 16)));
}
// split x into (hi bf16-in-upper-of-pair...) helper: builds packed hi & lo words
__device__ __forceinline__ void splitpack(float x, float y, uint32_t& hw, uint32_t& lw) {
    hw = pack2bf(y, x);                      // lower half = x (even k), upper = y
    lw = pack2bf(y - bf_hi(hw), x - bf_lo(hw));
}

__device__ __forceinline__ void mma_bf16(float* d, const uint32_t* a,
                                         uint32_t b0, uint32_t b1)
{
    asm volatile(
        "mma.sync.aligned.m16n8k16.row.col.f32.bf16.bf16.f32 "
        "{%0,%1,%2,%3}, {%4,%5,%6,%7}, {%8,%9}, {%0,%1,%2,%3};"
        : "+f"(d[0]), "+f"(d[1]), "+f"(d[2]), "+f"(d[3])
        : "r"(a[0]), "r"(a[1]), "r"(a[2]), "r"(a[3]), "r"(b0), "r"(b1));
}
__device__ __forceinline__ void mma_tf32(float* d,
    float a0, float a1, float a2, float a3, float b0, float b1)
{
    asm volatile(
        "mma.sync.aligned.m16n8k8.row.col.f32.tf32.tf32.f32 "
        "{%0,%1,%2,%3}, {%4,%5,%6,%7}, {%8,%9}, {%0,%1,%2,%3};"
        : "+f"(d[0]), "+f"(d[1]), "+f"(d[2]), "+f"(d[3])
        : "r"(__float_as_uint(a0)), "r"(__float_as_uint(a1)),
          "r"(__float_as_uint(a2)), "r"(__float_as_uint(a3)),
          "r"(__float_as_uint(b0)), "r"(__float_as_uint(b1)));
}
#define CPASYNC16(saddr, gptr) \
    asm volatile("cp.async.cg.shared.global [%0], [%1], 16;" :: "r"(saddr), "l"(gptr) : "memory")
#define CPCOMMIT() asm volatile("cp.async.commit_group;" ::: "memory")
#define CPWAIT(n)  asm volatile("cp.async.wait_group %0;" :: "n"(n) : "memory")

// ==================== prep: fp32 -> bf16 hi/lo splits =======================
__global__ __launch_bounds__(256) void prep_A(
    const float* __restrict__ hid, const float* __restrict__ enc)
{
    size_t gid = (size_t)blockIdx.x * 256 + threadIdx.x;
    size_t e = gid * 4;
    if (e >= (size_t)S_TOT * DM) return;
    const float* src = (e < (size_t)S_TXT * DM) ? enc + e : hid + (e - (size_t)S_TXT * DM);
    float4 v = *(const float4*)src;
    uint32_t h0, l0, h1, l1;
    splitpack(v.x, v.y, h0, l0);
    splitpack(v.z, v.w, h1, l1);
    *(uint2*)(g_Ah + e) = make_uint2(h0, h1);
    *(uint2*)(g_Al + e) = make_uint2(l0, l1);
}

__global__ __launch_bounds__(256) void prep_W(
    const float* __restrict__ W0, const float* __restrict__ W1,
    const float* __restrict__ W2, const float* __restrict__ W3)
{
    size_t gid = (size_t)blockIdx.x * 256 + threadIdx.x;
    size_t e = gid * 4;
    if (e >= (size_t)DM * DM) return;
    int w = blockIdx.y;
    const float* src = (w == 0) ? W0 : (w == 1) ? W1 : (w == 2) ? W2 : W3;
    float4 v = *(const float4*)(src + e);
    size_t o = (size_t)w * DM * DM + e;
    uint32_t h0, l0, h1, l1;
    splitpack(v.x, v.y, h0, l0);
    splitpack(v.z, v.w, h1, l1);
    *(uint2*)(g_Wh + o) = make_uint2(h0, h1);
    *(uint2*)(g_Wl + o) = make_uint2(l0, l1);
}

// ========== 3-term bf16 GEMM, BK=16, 4-stage cp.async pipeline ==============
// smem words/row = 20: words 0-7 hi (k0..15), 8-15 lo, 16-19 pad (conflict-free)
#define GSTRIDE 20
#define GSTAGE  (128 * GSTRIDE)
#define GEMM_SMEM_BYTES (8 * GSTAGE * 4)

__global__ __launch_bounds__(256, 2) void gemm_mma(
    const __nv_bfloat16* __restrict__ Ah, const __nv_bfloat16* __restrict__ Al,
    const __nv_bfloat16* __restrict__ Bh, const __nv_bfloat16* __restrict__ Bl,
    const float* __restrict__ bias, float* __restrict__ C,
    int swap_mode, int round_out)
{
    extern __shared__ uint32_t dsm[];
    uint32_t* Aw = dsm;
    uint32_t* Bw = dsm + 4 * GSTAGE;
    const int tid = threadIdx.x, lane = tid & 31, warp = tid >> 5;
    const int wm = (warp >> 1) * 32, wn = (warp & 1) * 64;
    const int m0 = blockIdx.y * 128, n0 = blockIdx.x * 128;
    const int r0 = lane >> 2, c0 = lane & 3;
    const int lrow = tid >> 1, lsub = tid & 1;
    const uint32_t sbA = smem_u32(Aw), sbB = smem_u32(Bw);

    float acc[2][8][4];
    #pragma unroll
    for (int i = 0; i < 2; i++)
        #pragma unroll
        for (int j = 0; j < 8; j++)
            #pragma unroll
            for (int c = 0; c < 4; c++) acc[i][j][c] = 0.f;

    auto load_stage = [&](int buf, int kt) {
        size_t ga = (size_t)(m0 + lrow) * DM + kt * 16 + lsub * 8;
        size_t gb = (size_t)(n0 + lrow) * DM + kt * 16 + lsub * 8;
        uint32_t dh = (buf * GSTAGE + lrow * GSTRIDE + lsub * 4) * 4;
        uint32_t dl = dh + 32;
        CPASYNC16(sbA + dh, Ah + ga);
        CPASYNC16(sbA + dl, Al + ga);
        CPASYNC16(sbB + dh, Bh + gb);
        CPASYNC16(sbB + dl, Bl + gb);
    };

    const int NKT = DM / 16;  // 120
    #pragma unroll
    for (int p = 0; p < 3; p++) { load_stage(p, p); CPCOMMIT(); }

    for (int kt = 0; kt < NKT; kt++) {
        int s = kt & 3;
        CPWAIT(2);
        __syncthreads();
        if (kt + 3 < NKT) load_stage((kt + 3) & 3, kt + 3);
        CPCOMMIT();

        const uint32_t* Ab = Aw + s * GSTAGE;
        const uint32_t* Bb = Bw + s * GSTAGE;
        uint32_t ah[2][4], al[2][4];
        #pragma unroll
        for (int i = 0; i < 2; i++) {
            int base = (wm + i * 16 + r0) * GSTRIDE + c0;
            ah[i][0] = Ab[base];            ah[i][1] = Ab[base + 8 * GSTRIDE];
            ah[i][2] = Ab[base + 4];        ah[i][3] = Ab[base + 8 * GSTRIDE + 4];
            al[i][0] = Ab[base + 8];        al[i][1] = Ab[base + 8 * GSTRIDE + 8];
            al[i][2] = Ab[base + 12];       al[i][3] = Ab[base + 8 * GSTRIDE + 12];
        }
        #pragma unroll
        for (int j = 0; j < 8; j++) {
            int rb = (wn + j * 8 + r0) * GSTRIDE + c0;
            uint32_t bh0 = Bb[rb],     bh1 = Bb[rb + 4];
            uint32_t bl0 = Bb[rb + 8], bl1 = Bb[rb + 12];
            #pragma unroll
            for (int i = 0; i < 2; i++) {
                mma_bf16(acc[i][j], ah[i], bh0, bh1);
                mma_bf16(acc[i][j], al[i], bh0, bh1);
                mma_bf16(acc[i][j], ah[i], bl0, bl1);
            }
        }
    }

    #pragma unroll
    for (int i = 0; i < 2; i++) {
        int row_lo = m0 + wm + i * 16 + r0;
        #pragma unroll
        for (int half = 0; half < 2; half++) {
            int row = row_lo + half * 8;
            size_t orow = (size_t)row;
            if (swap_mode)
                orow = (row < S_TXT) ? (size_t)(S_IMG + row) : (size_t)(row - S_TXT);
            float* dst = C + orow * DM + n0 + wn;
            #pragma unroll
            for (int j = 0; j < 8; j++) {
                int col = j * 8 + c0 * 2;
                float2 o;
                o.x = acc[i][j][half * 2 + 0] + __ldg(bias + n0 + wn + col);
                o.y = acc[i][j][half * 2 + 1] + __ldg(bias + n0 + wn + col + 1);
                if (round_out) { o.x = to_tf32(o.x); o.y = to_tf32(o.y); }
                *(float2*)(dst + col) = o;
            }
        }
    }
}

// ===== LayerNorm + RoPE: Q -> fp32 in place; K -> bf16 hi/lo split arrays ===
__global__ __launch_bounds__(256) void ln_rope(
    const float* __restrict__ cosb, const float* __restrict__ sinb)
{
    int which = blockIdx.y;
    const float* __restrict__ X = which ? g_K : g_Q;
    int w = blockIdx.x * 8 + (threadIdx.x >> 5);
    int lane = threadIdx.x & 31;
    int s = w / NH, h = w - s * NH;
    if (s >= S_TOT) return;

    size_t off = (size_t)s * DM + h * HD;
    float x0 = X[off + lane], x1 = X[off + lane + 32];
    float sum = x0 + x1;
    #pragma unroll
    for (int o = 16; o; o >>= 1) sum += __shfl_xor_sync(0xffffffffu, sum, o);
    float mu = sum * (1.0f / 64.0f);
    float d0 = x0 - mu, d1 = x1 - mu;
    float vs = fmaf(d0, d0, d1 * d1);
    #pragma unroll
    for (int o = 16; o; o >>= 1) vs += __shfl_xor_sync(0xffffffffu, vs, o);
    float inv = rsqrtf(fmaf(vs, 1.0f / 64.0f, 1e-5f));
    float y0 = d0 * inv, y1 = d1 * inv;

    if (s >= S_TXT) {
        int sp = s - S_TXT;
        const float* cr = cosb + (size_t)sp * HD;
        const float* sr = sinb + (size_t)sp * HD;
        float c0 = cr[lane], c1 = cr[lane + 32];
        float s0 = sr[lane], s1 = sr[lane + 32];
        float o0 = fmaf(y0, c0, -y1 * s0);
        float o1 = fmaf(y1, c1,  y0 * s1);
        y0 = o0; y1 = o1;
    }
    if (which) {
        __nv_bfloat16 h0 = __float2bfloat16(y0), h1 = __float2bfloat16(y1);
        g_Khb[off + lane]      = h0;
        g_Khb[off + lane + 32] = h1;
        g_Klb[off + lane]      = __float2bfloat16(y0 - __bfloat162float(h0));
        g_Klb[off + lane + 32] = __float2bfloat16(y1 - __bfloat162float(h1));
    } else {
        g_Q[off + lane] = y0;
        g_Q[off + lane + 32] = y1;
    }
}

// ============ flash attention: bf16 3-term QK + tf32 PV =====================
// smem: Ps[128][68] f32 | K[2][64 rows][68 words] (hi w0-31, lo w32-63) |
//       V[2][64][72] f32
#define AT_K  8704
#define AT_V  (8704 + 8704)
#define ATT_SMEM_BYTES ((8704 + 8704 + 9216) * 4)

__global__ __launch_bounds__(256, 1) void attn_mma()
{
    extern __shared__ float sm[];
    float* Ps = sm;
    const int h = blockIdx.y, m0 = blockIdx.x * 128;
    const int tid = threadIdx.x, lane = tid & 31, warp = tid >> 5;
    const int wm = warp * 16, r0 = lane >> 2, c0 = lane & 3;
    const uint32_t sK = smem_u32(sm + AT_K), sV = smem_u32(sm + AT_V);
    const float* Vs = sm + AT_V;

    // Q fragments: scaled, bf16 split, packed (4 k16 steps over HD=64)
    uint32_t qh[4][4], ql[4][4];
    const float* qb = g_Q + (size_t)(m0 + wm) * DM + h * HD;
    #pragma unroll
    for (int s = 0; s < 4; s++) {
        int d0 = s * 16 + 2 * c0;
        float2 e00 = *(const float2*)(qb + (size_t)r0 * DM + d0);
        float2 e10 = *(const float2*)(qb + (size_t)(r0 + 8) * DM + d0);
        float2 e01 = *(const float2*)(qb + (size_t)r0 * DM + d0 + 8);
        float2 e11 = *(const float2*)(qb + (size_t)(r0 + 8) * DM + d0 + 8);
        splitpack(QSCALE * e00.x, QSCALE * e00.y, qh[s][0], ql[s][0]);
        splitpack(QSCALE * e10.x, QSCALE * e10.y, qh[s][1], ql[s][1]);
        splitpack(QSCALE * e01.x, QSCALE * e01.y, qh[s][2], ql[s][2]);
        splitpack(QSCALE * e11.x, QSCALE * e11.y, qh[s][3], ql[s][3]);
    }

    float out[8][4];
    #pragma unroll
    for (int j = 0; j < 8; j++)
        #pragma unroll
        for (int c = 0; c < 4; c++) out[j][c] = 0.f;
    float mx0 = -1e30f, mx1 = -1e30f, l0 = 0.f, l1 = 0.f;

    auto load_kv = [&](int buf, int t) {
        int n0 = t * 64;
        #pragma unroll
        for (int i = 0; i < 4; i++) {   // K: 64 rows x (hi 128B + lo 128B)
            int f = tid + 256 * i, row = f >> 4, ch = f & 15;
            size_t g = (size_t)(n0 + row) * DM + h * HD;
            const __nv_bfloat16* src = (ch < 8) ? (g_Khb + g + ch * 8)
                                                : (g_Klb + g + (ch - 8) * 8);
            CPASYNC16(sK + (buf * 17408) + row * 272 + ch * 16, src);
        }
        #pragma unroll
        for (int i = 0; i < 4; i++) {   // V: 64 rows x 256B fp32
            int f = tid + 256 * i, row = f >> 4, ch = f & 15;
            size_t g = (size_t)(n0 + row) * DM + h * HD + ch * 4;
            CPASYNC16(sV + (buf * 18432) + row * 288 + ch * 16, g_V + g);
        }
        CPCOMMIT();
    };
    load_kv(0, 0);

    const int NT = S_TOT / 64;  // 52
    for (int t = 0; t < NT; t++) {
        int buf = t & 1;
        CPWAIT(0);
        __syncthreads();
        if (t + 1 < NT) load_kv(buf ^ 1, t + 1);

        // scores = Q @ K^T (log2 domain), bf16 3-term
        float s_[8][4];
        #pragma unroll
        for (int j = 0; j < 8; j++)
            #pragma unroll
            for (int c = 0; c < 4; c++) s_[j][c] = 0.f;
        const uint32_t* KWb = (const uint32_t*)(sm + AT_K) + buf * 4352;
        #pragma unroll
        for (int s = 0; s < 4; s++) {
            #pragma unroll
            for (int j = 0; j < 8; j++) {
                int rb = (j * 8 + r0) * 68 + s * 8 + c0;
                uint32_t bh0 = KWb[rb],      bh1 = KWb[rb + 4];
                uint32_t bl0 = KWb[rb + 32], bl1 = KWb[rb + 36];
                mma_bf16(s_[j], qh[s], bh0, bh1);
                mma_bf16(s_[j], ql[s], bh0, bh1);
                mma_bf16(s_[j], qh[s], bl0, bl1);
            }
        }

        // online softmax (rows wm+r0, wm+r0+8)
        float cm0 = -1e30f, cm1 = -1e30f;
        #pragma unroll
        for (int j = 0; j < 8; j++) {
            cm0 = fmaxf(cm0, fmaxf(s_[j][0], s_[j][1]));
            cm1 = fmaxf(cm1, fmaxf(s_[j][2], s_[j][3]));
        }
        cm0 = fmaxf(cm0, __shfl_xor_sync(0xffffffffu, cm0, 1));
        cm0 = fmaxf(cm0, __shfl_xor_sync(0xffffffffu, cm0, 2));
        cm1 = fmaxf(cm1, __shfl_xor_sync(0xffffffffu, cm1, 1));
        cm1 = fmaxf(cm1, __shfl_xor_sync(0xffffffffu, cm1, 2));
        float mn0 = fmaxf(mx0, cm0), mn1 = fmaxf(mx1, cm1);
        float corr0 = ex2(mx0 - mn0), corr1 = ex2(mx1 - mn1);
        mx0 = mn0; mx1 = mn1;

        float rs0 = 0.f, rs1 = 0.f;
        #pragma unroll
        for (int j = 0; j < 8; j++) {
            float p00 = to_tf32(ex2(s_[j][0] - mn0));
            float p01 = to_tf32(ex2(s_[j][1] - mn0));
            float p10 = to_tf32(ex2(s_[j][2] - mn1));
            float p11 = to_tf32(ex2(s_[j][3] - mn1));
            rs0 += p00 + p01; rs1 += p10 + p11;
            int col = j * 8 + 2 * c0;
            *(float2*)&Ps[(wm + r0) * 68 + col]     = make_float2(p00, p01);
            *(float2*)&Ps[(wm + r0 + 8) * 68 + col] = make_float2(p10, p11);
        }
        rs0 += __shfl_xor_sync(0xffffffffu, rs0, 1);
        rs0 += __shfl_xor_sync(0xffffffffu, rs0, 2);
        rs1 += __shfl_xor_sync(0xffffffffu, rs1, 1);
        rs1 += __shfl_xor_sync(0xffffffffu, rs1, 2);
        l0 = l0 * corr0 + rs0;
        l1 = l1 * corr1 + rs1;
        #pragma unroll
        for (int j = 0; j < 8; j++) {
            out[j][0] *= corr0; out[j][1] *= corr0;
            out[j][2] *= corr1; out[j][3] *= corr1;
        }
        __syncwarp();   // P rows wm..wm+15 are warp-private

        // out += P @ V (tf32; V pre-rounded by V-GEMM epilogue)
        const float* Vb = Vs + buf * 4608;
        #pragma unroll
        for (int kk = 0; kk < 8; kk++) {
            int col = kk * 8 + c0;
            float a0 = Ps[(wm + r0) * 68 + col];
            float a1 = Ps[(wm + r0 + 8) * 68 + col];
            float a2 = Ps[(wm + r0) * 68 + col + 4];
            float a3 = Ps[(wm + r0 + 8) * 68 + col + 4];
            #pragma unroll
            for (int j = 0; j < 8; j++) {
                float b0 = Vb[(kk * 8 + c0) * 72 + j * 8 + r0];
                float b1 = Vb[(kk * 8 + c0 + 4) * 72 + j * 8 + r0];
                mma_tf32(out[j], a0, a1, a2, a3, b0, b1);
            }
        }
    }

    // epilogue: write O as bf16 hi/lo split (feeds the final GEMM directly)
    float inv0 = 1.0f / l0, inv1 = 1.0f / l1;
    size_t q0 = (size_t)(m0 + wm + r0);
    #pragma unroll
    for (int j = 0; j < 8; j++) {
        int d = j * 8 + 2 * c0;
        size_t o0 = q0 * DM + h * HD + d;
        size_t o1 = (q0 + 8) * DM + h * HD + d;
        uint32_t hw, lw;
        splitpack(out[j][0] * inv0, out[j][1] * inv0, hw, lw);
        *(uint32_t*)(g_Oh + o0) = hw;
        *(uint32_t*)(g_Ol + o0) = lw;
        splitpack(out[j][2] * inv1, out[j][3] * inv1, hw, lw);
        *(uint32_t*)(g_Oh + o1) = hw;
        *(uint32_t*)(g_Ol + o1) = lw;
    }
}

// ---------------------------------------------------------------------------
extern "C" void kernel_launch(void* const* d_in, const int* in_sizes, int n_in,
                              void* d_out, int out_size)
{
    const float* hid = (const float*)d_in[0];
    const float* enc = (const float*)d_in[1];
    const float* rc  = (const float*)d_in[2];
    const float* rs  = (const float*)d_in[3];
    const float* Wq  = (const float*)d_in[4];
    const float* bq  = (const float*)d_in[5];
    const float* Wk  = (const float*)d_in[6];
    const float* bk  = (const float*)d_in[7];
    const float* Wv  = (const float*)d_in[8];
    const float* bv  = (const float*)d_in[9];
    const float* Wo  = (const float*)d_in[10];
    const float* bo  = (const float*)d_in[11];
    float* out = (float*)d_out;

    cudaFuncSetAttribute(gemm_mma, cudaFuncAttributeMaxDynamicSharedMemorySize, GEMM_SMEM_BYTES);
    cudaFuncSetAttribute(attn_mma, cudaFuncAttributeMaxDynamicSharedMemorySize, ATT_SMEM_BYTES);

    float* pQ; cudaGetSymbolAddress((void**)&pQ, g_Q);
    float* pK; cudaGetSymbolAddress((void**)&pK, g_K);
    float* pV; cudaGetSymbolAddress((void**)&pV, g_V);
    __nv_bfloat16* pAh; cudaGetSymbolAddress((void**)&pAh, g_Ah);
    __nv_bfloat16* pAl; cudaGetSymbolAddress((void**)&pAl, g_Al);
    __nv_bfloat16* pWh; cudaGetSymbolAddress((void**)&pWh, g_Wh);
    __nv_bfloat16* pWl; cudaGetSymbolAddress((void**)&pWl, g_Wl);
    __nv_bfloat16* pOh; cudaGetSymbolAddress((void**)&pOh, g_Oh);
    __nv_bfloat16* pOl; cudaGetSymbolAddress((void**)&pOl, g_Ol);

    const size_t WSZ = (size_t)DM * DM;
    dim3 gGemm(DM / 128, S_TOT / 128);   // (15, 26)

    prep_A<<<(S_TOT * DM / 4 + 255) / 256, 256>>>(hid, enc);                 // 1
    prep_W<<<dim3((DM * DM / 4 + 255) / 256, 4), 256>>>(Wq, Wk, Wv, Wo);     // 2
    gemm_mma<<<gGemm, 256, GEMM_SMEM_BYTES>>>(pAh, pAl, pWh + 0 * WSZ, pWl + 0 * WSZ, bq, pQ, 0, 0); // 3
    gemm_mma<<<gGemm, 256, GEMM_SMEM_BYTES>>>(pAh, pAl, pWh + 1 * WSZ, pWl + 1 * WSZ, bk, pK, 0, 0); // 4
    ln_rope<<<dim3((S_TOT * NH) / 8, 2), 256>>>(rc, rs);                     // 5
    // 6th launch -> ncu -s 5 -c 1 window
    gemm_mma<<<gGemm, 256, GEMM_SMEM_BYTES>>>(pAh, pAl, pWh + 2 * WSZ, pWl + 2 * WSZ, bv, pV, 0, 1); // 6
    attn_mma<<<dim3(S_TOT / 128, NH), 256, ATT_SMEM_BYTES>>>();              // 7
    gemm_mma<<<gGemm, 256, GEMM_SMEM_BYTES>>>(pOh, pOl, pWh + 3 * WSZ, pWl + 3 * WSZ, bo, out, 1, 0); // 8
}

// round 9
// speedup vs baseline: 2.2527x; 1.1186x over previous
#include <cuda_runtime.h>
#include <cuda_bf16.h>
#include <cstdint>

#define S_TOT 3328
#define S_TXT 256
#define S_IMG 3072
#define DM    1920
#define NH    30
#define HD    64
#define QSCALE 0.18033688011112043f  // 0.125*log2(e)

// fp32 scratch
__device__ float g_Q[(size_t)S_TOT * DM];
__device__ float g_K[(size_t)S_TOT * DM];
__device__ float g_V[(size_t)S_TOT * DM];
// bf16 hi/lo split operands
__device__ __nv_bfloat16 g_Ah[(size_t)S_TOT * DM];
__device__ __nv_bfloat16 g_Al[(size_t)S_TOT * DM];
__device__ __nv_bfloat16 g_Wh[4 * (size_t)DM * DM];
__device__ __nv_bfloat16 g_Wl[4 * (size_t)DM * DM];
__device__ __nv_bfloat16 g_Khb[(size_t)S_TOT * DM];
__device__ __nv_bfloat16 g_Klb[(size_t)S_TOT * DM];
__device__ __nv_bfloat16 g_Oh[(size_t)S_TOT * DM];
__device__ __nv_bfloat16 g_Ol[(size_t)S_TOT * DM];

__device__ __forceinline__ float to_tf32(float x) {
    uint32_t b; asm("cvt.rna.tf32.f32 %0, %1;" : "=r"(b) : "f"(x));
    return __uint_as_float(b);
}
__device__ __forceinline__ float ex2(float x) {
    float r; asm("ex2.approx.f32 %0, %1;" : "=f"(r) : "f"(x)); return r;
}
__device__ __forceinline__ uint32_t smem_u32(const void* p) {
    uint32_t a;
    asm("{ .reg .u64 t; cvta.to.shared.u64 t, %1; cvt.u32.u64 %0, t; }" : "=r"(a) : "l"(p));
    return a;
}
__device__ __forceinline__ uint32_t pack2bf(float up, float lo) {
    uint32_t r; asm("cvt.rn.bf16x2.f32 %0, %1, %2;" : "=r"(r) : "f"(up), "f"(lo));
    return r;
}
__device__ __forceinline__ float bf_lo(uint32_t u) {
    return __bfloat162float(__ushort_as_bfloat16((unsigned short)(u & 0xFFFFu)));
}
__device__ __forceinline__ float bf_hi(uint32_t u) {
    return __bfloat162float(__ushort_as_bfloat16((unsigned short)(u >> 16)));
}
__device__ __forceinline__ void splitpack(float x, float y, uint32_t& hw, uint32_t& lw) {
    hw = pack2bf(y, x);
    lw = pack2bf(y - bf_hi(hw), x - bf_lo(hw));
}
__device__ __forceinline__ void mma_bf16(float* d, const uint32_t* a,
                                         uint32_t b0, uint32_t b1)
{
    asm volatile(
        "mma.sync.aligned.m16n8k16.row.col.f32.bf16.bf16.f32 "
        "{%0,%1,%2,%3}, {%4,%5,%6,%7}, {%8,%9}, {%0,%1,%2,%3};"
        : "+f"(d[0]), "+f"(d[1]), "+f"(d[2]), "+f"(d[3])
        : "r"(a[0]), "r"(a[1]), "r"(a[2]), "r"(a[3]), "r"(b0), "r"(b1));
}
__device__ __forceinline__ void mma_tf32(float* d,
    float a0, float a1, float a2, float a3, float b0, float b1)
{
    asm volatile(
        "mma.sync.aligned.m16n8k8.row.col.f32.tf32.tf32.f32 "
        "{%0,%1,%2,%3}, {%4,%5,%6,%7}, {%8,%9}, {%0,%1,%2,%3};"
        : "+f"(d[0]), "+f"(d[1]), "+f"(d[2]), "+f"(d[3])
        : "r"(__float_as_uint(a0)), "r"(__float_as_uint(a1)),
          "r"(__float_as_uint(a2)), "r"(__float_as_uint(a3)),
          "r"(__float_as_uint(b0)), "r"(__float_as_uint(b1)));
}
#define CPASYNC16(saddr, gptr) \
    asm volatile("cp.async.cg.shared.global [%0], [%1], 16;" :: "r"(saddr), "l"(gptr) : "memory")
#define CPCOMMIT() asm volatile("cp.async.commit_group;" ::: "memory")
#define CPWAIT(n)  asm volatile("cp.async.wait_group %0;" :: "n"(n) : "memory")

// ==================== prep: fp32 -> bf16 hi/lo splits =======================
__global__ __launch_bounds__(256) void prep_A(
    const float* __restrict__ hid, const float* __restrict__ enc)
{
    size_t e = ((size_t)blockIdx.x * 256 + threadIdx.x) * 4;
    if (e >= (size_t)S_TOT * DM) return;
    const float* src = (e < (size_t)S_TXT * DM) ? enc + e : hid + (e - (size_t)S_TXT * DM);
    float4 v = *(const float4*)src;
    uint32_t h0, l0, h1, l1;
    splitpack(v.x, v.y, h0, l0);
    splitpack(v.z, v.w, h1, l1);
    *(uint2*)(g_Ah + e) = make_uint2(h0, h1);
    *(uint2*)(g_Al + e) = make_uint2(l0, l1);
}

__global__ __launch_bounds__(256) void prep_W(
    const float* __restrict__ W0, const float* __restrict__ W1,
    const float* __restrict__ W2, const float* __restrict__ W3)
{
    size_t e = ((size_t)blockIdx.x * 256 + threadIdx.x) * 4;
    if (e >= (size_t)DM * DM) return;
    int w = blockIdx.y;
    const float* src = (w == 0) ? W0 : (w == 1) ? W1 : (w == 2) ? W2 : W3;
    float4 v = *(const float4*)(src + e);
    size_t o = (size_t)w * DM * DM + e;
    uint32_t h0, l0, h1, l1;
    splitpack(v.x, v.y, h0, l0);
    splitpack(v.z, v.w, h1, l1);
    *(uint2*)(g_Wh + o) = make_uint2(h0, h1);
    *(uint2*)(g_Wl + o) = make_uint2(l0, l1);
}

// ========== 3-term bf16 GEMM, BK=16, 4-stage pipeline, z = weight id ========
#define GSTRIDE 20
#define GSTAGE  (128 * GSTRIDE)
#define GEMM_SMEM_BYTES (8 * GSTAGE * 4)

__global__ __launch_bounds__(256, 2) void gemm_mma(
    const __nv_bfloat16* __restrict__ Ah, const __nv_bfloat16* __restrict__ Al,
    const __nv_bfloat16* __restrict__ WhB, const __nv_bfloat16* __restrict__ WlB,
    const float* __restrict__ b0p, const float* __restrict__ b1p,
    const float* __restrict__ b2p,
    float* __restrict__ C0, float* __restrict__ C1, float* __restrict__ C2,
    int swap_mode, int round_mask)
{
    extern __shared__ uint32_t dsm[];
    uint32_t* Aw = dsm;
    uint32_t* Bw = dsm + 4 * GSTAGE;
    const int wsel = blockIdx.z;
    const __nv_bfloat16* Bh = WhB + (size_t)wsel * DM * DM;
    const __nv_bfloat16* Bl = WlB + (size_t)wsel * DM * DM;
    const float* bias = (wsel == 0) ? b0p : (wsel == 1) ? b1p : b2p;
    float* C = (wsel == 0) ? C0 : (wsel == 1) ? C1 : C2;
    const int round_out = (round_mask >> wsel) & 1;

    const int tid = threadIdx.x, lane = tid & 31, warp = tid >> 5;
    const int wm = (warp >> 1) * 32, wn = (warp & 1) * 64;
    const int m0 = blockIdx.y * 128, n0 = blockIdx.x * 128;
    const int r0 = lane >> 2, c0 = lane & 3;
    const int lrow = tid >> 1, lsub = tid & 1;
    const uint32_t sbA = smem_u32(Aw), sbB = smem_u32(Bw);

    float acc[2][8][4];
    #pragma unroll
    for (int i = 0; i < 2; i++)
        #pragma unroll
        for (int j = 0; j < 8; j++)
            #pragma unroll
            for (int c = 0; c < 4; c++) acc[i][j][c] = 0.f;

    auto load_stage = [&](int buf, int kt) {
        size_t ga = (size_t)(m0 + lrow) * DM + kt * 16 + lsub * 8;
        size_t gb = (size_t)(n0 + lrow) * DM + kt * 16 + lsub * 8;
        uint32_t dh = (buf * GSTAGE + lrow * GSTRIDE + lsub * 4) * 4;
        uint32_t dl = dh + 32;
        CPASYNC16(sbA + dh, Ah + ga);
        CPASYNC16(sbA + dl, Al + ga);
        CPASYNC16(sbB + dh, Bh + gb);
        CPASYNC16(sbB + dl, Bl + gb);
    };

    const int NKT = DM / 16;  // 120
    #pragma unroll
    for (int p = 0; p < 3; p++) { load_stage(p, p); CPCOMMIT(); }

    for (int kt = 0; kt < NKT; kt++) {
        int s = kt & 3;
        CPWAIT(2);
        __syncthreads();
        if (kt + 3 < NKT) load_stage((kt + 3) & 3, kt + 3);
        CPCOMMIT();

        const uint32_t* Ab = Aw + s * GSTAGE;
        const uint32_t* Bb = Bw + s * GSTAGE;
        uint32_t ah[2][4], al[2][4];
        #pragma unroll
        for (int i = 0; i < 2; i++) {
            int base = (wm + i * 16 + r0) * GSTRIDE + c0;
            ah[i][0] = Ab[base];            ah[i][1] = Ab[base + 8 * GSTRIDE];
            ah[i][2] = Ab[base + 4];        ah[i][3] = Ab[base + 8 * GSTRIDE + 4];
            al[i][0] = Ab[base + 8];        al[i][1] = Ab[base + 8 * GSTRIDE + 8];
            al[i][2] = Ab[base + 12];       al[i][3] = Ab[base + 8 * GSTRIDE + 12];
        }
        #pragma unroll
        for (int j = 0; j < 8; j++) {
            int rb = (wn + j * 8 + r0) * GSTRIDE + c0;
            uint32_t bh0 = Bb[rb],     bh1 = Bb[rb + 4];
            uint32_t bl0 = Bb[rb + 8], bl1 = Bb[rb + 12];
            #pragma unroll
            for (int i = 0; i < 2; i++) {
                mma_bf16(acc[i][j], ah[i], bh0, bh1);
                mma_bf16(acc[i][j], al[i], bh0, bh1);
                mma_bf16(acc[i][j], ah[i], bl0, bl1);
            }
        }
    }

    #pragma unroll
    for (int i = 0; i < 2; i++) {
        int row_lo = m0 + wm + i * 16 + r0;
        #pragma unroll
        for (int half = 0; half < 2; half++) {
            int row = row_lo + half * 8;
            size_t orow = (size_t)row;
            if (swap_mode)
                orow = (row < S_TXT) ? (size_t)(S_IMG + row) : (size_t)(row - S_TXT);
            float* dst = C + orow * DM + n0 + wn;
            #pragma unroll
            for (int j = 0; j < 8; j++) {
                int col = j * 8 + c0 * 2;
                float2 o;
                o.x = acc[i][j][half * 2 + 0] + __ldg(bias + n0 + wn + col);
                o.y = acc[i][j][half * 2 + 1] + __ldg(bias + n0 + wn + col + 1);
                if (round_out) { o.x = to_tf32(o.x); o.y = to_tf32(o.y); }
                *(float2*)(dst + col) = o;
            }
        }
    }
}

// ===== LayerNorm + RoPE: Q -> fp32 in place; K -> bf16 hi/lo split arrays ===
__global__ __launch_bounds__(256) void ln_rope(
    const float* __restrict__ cosb, const float* __restrict__ sinb, int which)
{
    const float* __restrict__ X = which ? g_K : g_Q;
    int w = blockIdx.x * 8 + (threadIdx.x >> 5);
    int lane = threadIdx.x & 31;
    int s = w / NH, h = w - s * NH;
    if (s >= S_TOT) return;

    size_t off = (size_t)s * DM + h * HD;
    float x0 = X[off + lane], x1 = X[off + lane + 32];
    float sum = x0 + x1;
    #pragma unroll
    for (int o = 16; o; o >>= 1) sum += __shfl_xor_sync(0xffffffffu, sum, o);
    float mu = sum * (1.0f / 64.0f);
    float d0 = x0 - mu, d1 = x1 - mu;
    float vs = fmaf(d0, d0, d1 * d1);
    #pragma unroll
    for (int o = 16; o; o >>= 1) vs += __shfl_xor_sync(0xffffffffu, vs, o);
    float inv = rsqrtf(fmaf(vs, 1.0f / 64.0f, 1e-5f));
    float y0 = d0 * inv, y1 = d1 * inv;

    if (s >= S_TXT) {
        int sp = s - S_TXT;
        const float* cr = cosb + (size_t)sp * HD;
        const float* sr = sinb + (size_t)sp * HD;
        float c0 = cr[lane], c1 = cr[lane + 32];
        float s0 = sr[lane], s1 = sr[lane + 32];
        float o0 = fmaf(y0, c0, -y1 * s0);
        float o1 = fmaf(y1, c1,  y0 * s1);
        y0 = o0; y1 = o1;
    }
    if (which) {
        __nv_bfloat16 h0 = __float2bfloat16(y0), h1 = __float2bfloat16(y1);
        g_Khb[off + lane]      = h0;
        g_Khb[off + lane + 32] = h1;
        g_Klb[off + lane]      = __float2bfloat16(y0 - __bfloat162float(h0));
        g_Klb[off + lane + 32] = __float2bfloat16(y1 - __bfloat162float(h1));
    } else {
        g_Q[off + lane] = y0;
        g_Q[off + lane + 32] = y1;
    }
}

// ====== flash attention: 256-q tiles, bf16 3-term QK + tf32 PV ==============
// smem floats: Ps[256][68]=17408 | K[2][64][68 w] u32 =8704 | V[2][64][72]=9216
#define AT_K  17408
#define AT_V  (17408 + 8704)
#define ATT_SMEM_BYTES ((17408 + 8704 + 9216) * 4)

__global__ __launch_bounds__(256, 1) void attn_mma()
{
    extern __shared__ float sm[];
    float* Ps = sm;
    const int h = blockIdx.y, m0 = blockIdx.x * 256;
    const int tid = threadIdx.x, lane = tid & 31, warp = tid >> 5;
    const int wm = warp * 32, r0 = lane >> 2, c0 = lane & 3;
    const uint32_t sK = smem_u32(sm + AT_K), sV = smem_u32(sm + AT_V);
    const float* Vs = sm + AT_V;

    // Q fragments: 2 row-blocks x 4 k16-steps, scaled + bf16 split
    uint32_t qh[2][4][4], ql[2][4][4];
    #pragma unroll
    for (int b = 0; b < 2; b++) {
        const float* qb = g_Q + (size_t)(m0 + wm + 16 * b) * DM + h * HD;
        #pragma unroll
        for (int s = 0; s < 4; s++) {
            int d0 = s * 16 + 2 * c0;
            float2 e00 = *(const float2*)(qb + (size_t)r0 * DM + d0);
            float2 e10 = *(const float2*)(qb + (size_t)(r0 + 8) * DM + d0);
            float2 e01 = *(const float2*)(qb + (size_t)r0 * DM + d0 + 8);
            float2 e11 = *(const float2*)(qb + (size_t)(r0 + 8) * DM + d0 + 8);
            splitpack(QSCALE * e00.x, QSCALE * e00.y, qh[b][s][0], ql[b][s][0]);
            splitpack(QSCALE * e10.x, QSCALE * e10.y, qh[b][s][1], ql[b][s][1]);
            splitpack(QSCALE * e01.x, QSCALE * e01.y, qh[b][s][2], ql[b][s][2]);
            splitpack(QSCALE * e11.x, QSCALE * e11.y, qh[b][s][3], ql[b][s][3]);
        }
    }

    float out[2][8][4];
    #pragma unroll
    for (int b = 0; b < 2; b++)
        #pragma unroll
        for (int j = 0; j < 8; j++)
            #pragma unroll
            for (int c = 0; c < 4; c++) out[b][j][c] = 0.f;
    float mx[2][2] = {{-1e30f, -1e30f}, {-1e30f, -1e30f}};
    float lsum[2][2] = {{0.f, 0.f}, {0.f, 0.f}};

    auto load_kv = [&](int buf, int t) {
        int n0 = t * 64;
        #pragma unroll
        for (int i = 0; i < 4; i++) {   // K: 64 rows x (hi 128B | lo 128B)
            int f = tid + 256 * i, row = f >> 4, ch = f & 15;
            size_t g = (size_t)(n0 + row) * DM + h * HD;
            const __nv_bfloat16* src = (ch < 8) ? (g_Khb + g + ch * 8)
                                                : (g_Klb + g + (ch - 8) * 8);
            CPASYNC16(sK + buf * 17408 + row * 272 + ch * 16, src);
        }
        #pragma unroll
        for (int i = 0; i < 4; i++) {   // V: 64 rows x 256B fp32
            int f = tid + 256 * i, row = f >> 4, ch = f & 15;
            size_t g = (size_t)(n0 + row) * DM + h * HD + ch * 4;
            CPASYNC16(sV + buf * 18432 + row * 288 + ch * 16, g_V + g);
        }
        CPCOMMIT();
    };
    load_kv(0, 0);

    const int NT = S_TOT / 64;  // 52
    for (int t = 0; t < NT; t++) {
        int buf = t & 1;
        CPWAIT(0);
        __syncthreads();
        if (t + 1 < NT) load_kv(buf ^ 1, t + 1);

        const uint32_t* KWb = (const uint32_t*)(sm + AT_K) + buf * 4352;

        #pragma unroll
        for (int b = 0; b < 2; b++) {
            float s_[8][4];
            #pragma unroll
            for (int j = 0; j < 8; j++)
                #pragma unroll
                for (int c = 0; c < 4; c++) s_[j][c] = 0.f;
            #pragma unroll
            for (int s = 0; s < 4; s++) {
                #pragma unroll
                for (int j = 0; j < 8; j++) {
                    int rb = (j * 8 + r0) * 68 + s * 8 + c0;
                    uint32_t bh0 = KWb[rb],      bh1 = KWb[rb + 4];
                    uint32_t bl0 = KWb[rb + 32], bl1 = KWb[rb + 36];
                    mma_bf16(s_[j], qh[b][s], bh0, bh1);
                    mma_bf16(s_[j], ql[b][s], bh0, bh1);
                    mma_bf16(s_[j], qh[b][s], bl0, bl1);
                }
            }

            float cm0 = -1e30f, cm1 = -1e30f;
            #pragma unroll
            for (int j = 0; j < 8; j++) {
                cm0 = fmaxf(cm0, fmaxf(s_[j][0], s_[j][1]));
                cm1 = fmaxf(cm1, fmaxf(s_[j][2], s_[j][3]));
            }
            cm0 = fmaxf(cm0, __shfl_xor_sync(0xffffffffu, cm0, 1));
            cm0 = fmaxf(cm0, __shfl_xor_sync(0xffffffffu, cm0, 2));
            cm1 = fmaxf(cm1, __shfl_xor_sync(0xffffffffu, cm1, 1));
            cm1 = fmaxf(cm1, __shfl_xor_sync(0xffffffffu, cm1, 2));
            float mn0 = fmaxf(mx[b][0], cm0), mn1 = fmaxf(mx[b][1], cm1);
            float corr0 = ex2(mx[b][0] - mn0), corr1 = ex2(mx[b][1] - mn1);
            mx[b][0] = mn0; mx[b][1] = mn1;

            float rs0 = 0.f, rs1 = 0.f;
            int prow0 = (wm + 16 * b + r0) * 68, prow1 = (wm + 16 * b + r0 + 8) * 68;
            #pragma unroll
            for (int j = 0; j < 8; j++) {
                float p00 = to_tf32(ex2(s_[j][0] - mn0));
                float p01 = to_tf32(ex2(s_[j][1] - mn0));
                float p10 = to_tf32(ex2(s_[j][2] - mn1));
                float p11 = to_tf32(ex2(s_[j][3] - mn1));
                rs0 += p00 + p01; rs1 += p10 + p11;
                int col = j * 8 + 2 * c0;
                *(float2*)&Ps[prow0 + col] = make_float2(p00, p01);
                *(float2*)&Ps[prow1 + col] = make_float2(p10, p11);
            }
            rs0 += __shfl_xor_sync(0xffffffffu, rs0, 1);
            rs0 += __shfl_xor_sync(0xffffffffu, rs0, 2);
            rs1 += __shfl_xor_sync(0xffffffffu, rs1, 1);
            rs1 += __shfl_xor_sync(0xffffffffu, rs1, 2);
            lsum[b][0] = lsum[b][0] * corr0 + rs0;
            lsum[b][1] = lsum[b][1] * corr1 + rs1;
            #pragma unroll
            for (int j = 0; j < 8; j++) {
                out[b][j][0] *= corr0; out[b][j][1] *= corr0;
                out[b][j][2] *= corr1; out[b][j][3] *= corr1;
            }
        }
        __syncwarp();   // P rows wm..wm+31 are warp-private

        // out += P @ V (tf32; V pre-rounded by V-GEMM epilogue)
        const float* Vb = Vs + buf * 4608;
        #pragma unroll
        for (int kk = 0; kk < 8; kk++) {
            int col = kk * 8 + c0;
            float a[2][4];
            #pragma unroll
            for (int b = 0; b < 2; b++) {
                a[b][0] = Ps[(wm + 16 * b + r0) * 68 + col];
                a[b][1] = Ps[(wm + 16 * b + r0 + 8) * 68 + col];
                a[b][2] = Ps[(wm + 16 * b + r0) * 68 + col + 4];
                a[b][3] = Ps[(wm + 16 * b + r0 + 8) * 68 + col + 4];
            }
            #pragma unroll
            for (int j = 0; j < 8; j++) {
                float b0 = Vb[(kk * 8 + c0) * 72 + j * 8 + r0];
                float b1 = Vb[(kk * 8 + c0 + 4) * 72 + j * 8 + r0];
                mma_tf32(out[0][j], a[0][0], a[0][1], a[0][2], a[0][3], b0, b1);
                mma_tf32(out[1][j], a[1][0], a[1][1], a[1][2], a[1][3], b0, b1);
            }
        }
    }

    // epilogue: O as bf16 hi/lo split (feeds final GEMM)
    #pragma unroll
    for (int b = 0; b < 2; b++) {
        float inv0 = 1.0f / lsum[b][0], inv1 = 1.0f / lsum[b][1];
        size_t q0 = (size_t)(m0 + wm + 16 * b + r0);
        #pragma unroll
        for (int j = 0; j < 8; j++) {
            int d = j * 8 + 2 * c0;
            size_t o0 = q0 * DM + h * HD + d;
            size_t o1 = (q0 + 8) * DM + h * HD + d;
            uint32_t hw, lw;
            splitpack(out[b][j][0] * inv0, out[b][j][1] * inv0, hw, lw);
            *(uint32_t*)(g_Oh + o0) = hw;
            *(uint32_t*)(g_Ol + o0) = lw;
            splitpack(out[b][j][2] * inv1, out[b][j][3] * inv1, hw, lw);
            *(uint32_t*)(g_Oh + o1) = hw;
            *(uint32_t*)(g_Ol + o1) = lw;
        }
    }
}

// ---------------------------------------------------------------------------
extern "C" void kernel_launch(void* const* d_in, const int* in_sizes, int n_in,
                              void* d_out, int out_size)
{
    const float* hid = (const float*)d_in[0];
    const float* enc = (const float*)d_in[1];
    const float* rc  = (const float*)d_in[2];
    const float* rs  = (const float*)d_in[3];
    const float* Wq  = (const float*)d_in[4];
    const float* bq  = (const float*)d_in[5];
    const float* Wk  = (const float*)d_in[6];
    const float* bk  = (const float*)d_in[7];
    const float* Wv  = (const float*)d_in[8];
    const float* bv  = (const float*)d_in[9];
    const float* Wo  = (const float*)d_in[10];
    const float* bo  = (const float*)d_in[11];
    float* out = (float*)d_out;

    cudaFuncSetAttribute(gemm_mma, cudaFuncAttributeMaxDynamicSharedMemorySize, GEMM_SMEM_BYTES);
    cudaFuncSetAttribute(attn_mma, cudaFuncAttributeMaxDynamicSharedMemorySize, ATT_SMEM_BYTES);

    float* pQ; cudaGetSymbolAddress((void**)&pQ, g_Q);
    float* pK; cudaGetSymbolAddress((void**)&pK, g_K);
    float* pV; cudaGetSymbolAddress((void**)&pV, g_V);
    __nv_bfloat16* pAh; cudaGetSymbolAddress((void**)&pAh, g_Ah);
    __nv_bfloat16* pAl; cudaGetSymbolAddress((void**)&pAl, g_Al);
    __nv_bfloat16* pWh; cudaGetSymbolAddress((void**)&pWh, g_Wh);
    __nv_bfloat16* pWl; cudaGetSymbolAddress((void**)&pWl, g_Wl);
    __nv_bfloat16* pOh; cudaGetSymbolAddress((void**)&pOh, g_Oh);
    __nv_bfloat16* pOl; cudaGetSymbolAddress((void**)&pOl, g_Ol);

    const size_t WSZ = (size_t)DM * DM;

    prep_A<<<(S_TOT * DM / 4 + 255) / 256, 256>>>(hid, enc);                 // 1
    prep_W<<<dim3((DM * DM / 4 + 255) / 256, 4), 256>>>(Wq, Wk, Wv, Wo);     // 2
    // merged QKV GEMM: grid.z = 3 -> 1170 CTAs, ~4 full waves
    gemm_mma<<<dim3(DM / 128, S_TOT / 128, 3), 256, GEMM_SMEM_BYTES>>>(       // 3
        pAh, pAl, pWh, pWl, bq, bk, bv, pQ, pK, pV, 0, 4 /* round V only */);
    ln_rope<<<(S_TOT * NH) / 8, 256>>>(rc, rs, 0);                           // 4
    ln_rope<<<(S_TOT * NH) / 8, 256>>>(rc, rs, 1);                           // 5
    // 6th launch -> ncu -s 5 -c 1 window
    attn_mma<<<dim3(S_TOT / 256, NH), 256, ATT_SMEM_BYTES>>>();              // 6
    gemm_mma<<<dim3(DM / 128, S_TOT / 128, 1), 256, GEMM_SMEM_BYTES>>>(       // 7
        pOh, pOl, pWh + 3 * WSZ, pWl + 3 * WSZ, bo, bo, bo, out, out, out, 1, 0);
}